// round 14
// baseline (speedup 1.0000x reference)
#include <cuda_runtime.h>
#include <cuda_fp16.h>
#include <cstdint>

#define NB 4
#define NS 512
#define ND 768
#define NL 64
#define KC 32
#define NCH 24           // 768 / 32
#define STAGES 5
#define THREADS 256
#define L_PER 2

// fp16 copies of inputs + rank-1 terms (bias folded into g_t2h)
__device__ float  g_t2h[NB * NL * NS];
__device__ float  g_t2d[NB * NL * NS];
__device__ __half g_head_h[(size_t)NB * NS * ND];
__device__ __half g_dep_h[(size_t)NB * NS * ND];
__device__ __half g_U_h[NL * ND];

// smem: U rows (2*768*2=3072B) | mbar pairs (5*16=80, pad to 128) | 5 stages of
// [A 128x32 pitch40 (10240B) | B 64x32 pitch40 (5120B)]
#define SM_U     0
#define SM_MBAR  3072
#define SM_TILES 3200
#define A_BYTES  10240
#define STAGE_BYTES 15360
#define SMEM_TOTAL (SM_TILES + STAGES * STAGE_BYTES)   // 80000 -> 2 CTAs/SM

static __device__ __forceinline__ uint32_t s2u(const void* p) {
    uint32_t a;
    asm("{ .reg .u64 t; cvta.to.shared.u64 t, %1; cvt.u32.u64 %0, t; }"
        : "=r"(a) : "l"(p));
    return a;
}
static __device__ __forceinline__ void cpa16(uint32_t s, const void* g) {
    asm volatile("cp.async.cg.shared.global [%0], [%1], 16;" :: "r"(s), "l"(g));
}
static __device__ __forceinline__ void mbar_init(uint32_t a, uint32_t cnt) {
    asm volatile("mbarrier.init.shared.b64 [%0], %1;" :: "r"(a), "r"(cnt) : "memory");
}
static __device__ __forceinline__ void mbar_arrive(uint32_t a) {
    asm volatile("mbarrier.arrive.shared.b64 _, [%0];" :: "r"(a) : "memory");
}
static __device__ __forceinline__ void cpa_mbar_arrive(uint32_t a) {
    asm volatile("cp.async.mbarrier.arrive.noinc.shared.b64 [%0];"
                 :: "r"(a) : "memory");
}
static __device__ __forceinline__ void mbar_wait(uint32_t a, uint32_t parity) {
    asm volatile(
        "{\n\t.reg .pred P;\n\t"
        "WL_%=:\n\t"
        "mbarrier.try_wait.parity.acquire.cta.shared::cta.b64 P, [%0], %1, 0x989680;\n\t"
        "@P bra.uni WD_%=;\n\t"
        "bra.uni WL_%=;\n\t"
        "WD_%=:\n\t}"
        :: "r"(a), "r"(parity) : "memory");
}
static __device__ __forceinline__ void ldsm4(uint32_t& r0, uint32_t& r1,
                                             uint32_t& r2, uint32_t& r3,
                                             uint32_t a) {
    asm volatile("ldmatrix.sync.aligned.m8n8.x4.shared.b16 {%0,%1,%2,%3}, [%4];"
                 : "=r"(r0), "=r"(r1), "=r"(r2), "=r"(r3) : "r"(a));
}
static __device__ __forceinline__ unsigned hm2(unsigned a, unsigned b) {
    __half2 x = *reinterpret_cast<__half2*>(&a);
    __half2 y = *reinterpret_cast<__half2*>(&b);
    __half2 r = __hmul2(x, y);
    return *reinterpret_cast<unsigned*>(&r);
}
static __device__ __forceinline__ unsigned pk2(float a, float b) {
    __half2 h = __floats2half2_rn(a, b);
    return *reinterpret_cast<unsigned*>(&h);
}

// ---------------------------------------------------------------------------
// prep_kernel: blocks [0,512) convert to fp16 (vectorized: 8 floats/thread
// per step, uint4 stores); blocks [512,640) rank-1 terms.
// ---------------------------------------------------------------------------
__global__ void prep_kernel(const float* __restrict__ head,
                            const float* __restrict__ dep,
                            const float* __restrict__ U,
                            const float* __restrict__ W,
                            const float* __restrict__ bias) {
    __shared__ float sX[32][36];
    __shared__ float sW[64][36];

    if (blockIdx.x < 512) {
        const size_t n8 = (size_t)NB * NS * ND / 8;
        const size_t stride = (size_t)512 * blockDim.x;
        for (size_t i = blockIdx.x * (size_t)blockDim.x + threadIdx.x; i < n8;
             i += stride) {
            float4 a = ((const float4*)head)[2 * i];
            float4 c = ((const float4*)head)[2 * i + 1];
            ((uint4*)g_head_h)[i] = make_uint4(pk2(a.x, a.y), pk2(a.z, a.w),
                                               pk2(c.x, c.y), pk2(c.z, c.w));
            a = ((const float4*)dep)[2 * i];
            c = ((const float4*)dep)[2 * i + 1];
            ((uint4*)g_dep_h)[i] = make_uint4(pk2(a.x, a.y), pk2(a.z, a.w),
                                              pk2(c.x, c.y), pk2(c.z, c.w));
        }
        const size_t u8 = (size_t)NL * ND / 8;
        for (size_t i = blockIdx.x * (size_t)blockDim.x + threadIdx.x; i < u8;
             i += stride) {
            float4 a = ((const float4*)U)[2 * i];
            float4 c = ((const float4*)U)[2 * i + 1];
            ((uint4*)g_U_h)[i] = make_uint4(pk2(a.x, a.y), pk2(a.z, a.w),
                                            pk2(c.x, c.y), pk2(c.z, c.w));
        }
        return;
    }

    int idx = blockIdx.x - 512;
    int type = idx >> 6;
    int b = (idx >> 4) & 3;
    int s0 = (idx & 15) * 32;
    const float* X = type ? dep : head;
    float* out = type ? g_t2d : g_t2h;
    int woff = type ? ND : 0;

    int t = threadIdx.x;
    int row = t >> 3, c4 = (t & 7) * 4;
    int ty = t >> 4, tx = t & 15;
    float acc[2][4] = {};

    for (int k0 = 0; k0 < ND; k0 += 32) {
        *(float4*)&sX[row][c4] =
            *(const float4*)&X[(size_t)(b * NS + s0 + row) * ND + k0 + c4];
        *(float4*)&sW[row][c4] =
            *(const float4*)&W[(size_t)row * (2 * ND) + woff + k0 + c4];
        *(float4*)&sW[row + 32][c4] =
            *(const float4*)&W[(size_t)(row + 32) * (2 * ND) + woff + k0 + c4];
        __syncthreads();
#pragma unroll
        for (int kk = 0; kk < 32; kk++) {
            float x0 = sX[ty * 2 + 0][kk];
            float x1 = sX[ty * 2 + 1][kk];
#pragma unroll
            for (int j = 0; j < 4; j++) {
                float w = sW[tx + 16 * j][kk];
                acc[0][j] += x0 * w;
                acc[1][j] += x1 * w;
            }
        }
        __syncthreads();
    }
#pragma unroll
    for (int rr = 0; rr < 2; rr++) {
        int s = s0 + ty * 2 + rr;
#pragma unroll
        for (int j = 0; j < 4; j++) {
            int ll = tx + 16 * j;
            float v = acc[rr][j];
            if (type == 0) v += bias[ll];
            out[(size_t)(b * NL + ll) * NS + s] = v;
        }
    }
}

// ---------------------------------------------------------------------------
// Main: per CTA: (b, 2 labels, 128 i x 64 o).
// LDSM once, MMA per label (U scaling on A frags via reused HMUL2 temps).
// NEW: both k-steps' fragments are loaded up front each chunk, so the ks1
// LDSM crossbar traffic drains underneath the ks0 MMA batch.
// 256 threads, 8 warps 4m x 2n, per-label warp tile 32x32, f32 acc.
// KC=32, 5 stages, 4 fills ahead, per-stage full/empty mbarriers. 2 CTAs/SM.
// ---------------------------------------------------------------------------
__global__ void __launch_bounds__(THREADS, 2) biaffine_main(float* __restrict__ out) {
    extern __shared__ char smem[];
    const uint32_t su = s2u(smem);
    __half* sU = (__half*)(smem + SM_U);

    const int tid = threadIdx.x;
    const int lane = tid & 31;
    const int wid = tid >> 5;
    const int rbase = (wid & 3) * 32;       // 4 warps in m (128 rows)
    const int cbase = (wid >> 2) * 32;      // 2 warps in n (64 cols)

    const int L0 = blockIdx.y * L_PER;
    const int b  = blockIdx.z;
    const int i0 = (blockIdx.x >> 3) * 128;
    const int o0 = (blockIdx.x & 7) * 64;

    // mbar layout: full[s] @ SM_MBAR+16s, empty[s] @ SM_MBAR+16s+8
    if (tid == 0) {
#pragma unroll
        for (int s = 0; s < STAGES; s++) {
            mbar_init(su + SM_MBAR + s * 16,     THREADS);  // full
            mbar_init(su + SM_MBAR + s * 16 + 8, THREADS);  // empty
        }
    }

    // Fill mapping.
    const int frow = tid >> 1;
    const int fh = (tid & 1) * 16;
    const __half* gA = g_head_h + ((size_t)(b * NS + i0 + frow)) * ND + fh;
    const uint32_t sfA = su + SM_TILES + (frow * 40 + fh) * 2;
    const int brow = tid >> 2;
    const int bh = (tid & 3) * 8;
    const __half* gB = g_dep_h + ((size_t)(b * NS + o0 + brow)) * ND + bh;
    const uint32_t sfB = su + SM_TILES + A_BYTES + (brow * 40 + bh) * 2;

    auto fill = [&](int s, int ch) {
        const int k0 = ch * KC;
        const uint32_t so = s * STAGE_BYTES;
        cpa16(sfA + so,      gA + k0);
        cpa16(sfA + so + 16, gA + k0 + 8);
        cpa16(sfB + so,      gB + k0);
    };

    // U rows for both labels (contiguous in g_U_h)
    {
        const uint32_t* gU = (const uint32_t*)(g_U_h + (size_t)L0 * ND);
        for (int j = tid; j < L_PER * ND / 2; j += THREADS)
            ((uint32_t*)sU)[j] = gU[j];
    }
    __syncthreads();   // mbar init + sU visible to all

    // Prologue: fill stages 0..3 (fresh, no empty wait needed).
#pragma unroll
    for (int p = 0; p < 4; p++) {
        fill(p, p);
        cpa_mbar_arrive(su + SM_MBAR + p * 16);
    }

    float acc[L_PER][2][4][4];
#pragma unroll
    for (int l = 0; l < L_PER; l++)
#pragma unroll
        for (int mi = 0; mi < 2; mi++)
#pragma unroll
            for (int ni = 0; ni < 4; ni++)
#pragma unroll
                for (int k = 0; k < 4; k++) acc[l][mi][ni][k] = 0.0f;

    const int lrow = (lane & 7) + ((lane >> 3) & 1) * 8;
    const int lcol = (lane >> 4) * 8;
    const int c0 = (lane & 3) * 2;

    int cs = 0, cph = 0;     // consumer stage/phase
    int ps = 4, pph = 1;     // producer: next fill = chunk 4 -> stage 4
    for (int ch = 0; ch < NCH; ch++) {
        // consumer: wait chunk ch ready
        mbar_wait(su + SM_MBAR + cs * 16, cph);

        const uint32_t aB = su + SM_TILES + cs * STAGE_BYTES;
        const uint32_t bB = aB + A_BYTES;

        // Load BOTH k-steps' fragments up front; ks1's LDSMs drain under
        // the ks0 MMA batch.
        unsigned af[2][2][4], bf[2][4][2];
#pragma unroll
        for (int ks = 0; ks < 2; ks++) {
            const int kb = ks * 16;
#pragma unroll
            for (int mi = 0; mi < 2; mi++) {
                uint32_t a = aB + ((rbase + mi * 16 + lrow) * 40 + kb + lcol) * 2;
                ldsm4(af[ks][mi][0], af[ks][mi][1], af[ks][mi][2], af[ks][mi][3], a);
            }
            {
                uint32_t a = bB + ((cbase + lrow) * 40 + kb + lcol) * 2;
                ldsm4(bf[ks][0][0], bf[ks][1][0], bf[ks][0][1], bf[ks][1][1], a);
                a = bB + ((cbase + 16 + lrow) * 40 + kb + lcol) * 2;
                ldsm4(bf[ks][2][0], bf[ks][3][0], bf[ks][2][1], bf[ks][3][1], a);
            }
        }

#pragma unroll
        for (int ks = 0; ks < 2; ks++) {
            const int kg = ch * KC + ks * 16;
#pragma unroll
            for (int l = 0; l < L_PER; l++) {
                unsigned ulo = *(const unsigned*)&sU[l * ND + kg + c0];
                unsigned uhi = *(const unsigned*)&sU[l * ND + kg + c0 + 8];
#pragma unroll
                for (int mi = 0; mi < 2; mi++) {
                    unsigned a0 = hm2(af[ks][mi][0], ulo);
                    unsigned a1 = hm2(af[ks][mi][1], ulo);
                    unsigned a2 = hm2(af[ks][mi][2], uhi);
                    unsigned a3 = hm2(af[ks][mi][3], uhi);
#pragma unroll
                    for (int ni = 0; ni < 4; ni++) {
                        asm volatile(
                            "mma.sync.aligned.m16n8k16.row.col.f32.f16.f16.f32 "
                            "{%0,%1,%2,%3}, {%4,%5,%6,%7}, {%8,%9}, {%0,%1,%2,%3};"
                            : "+f"(acc[l][mi][ni][0]), "+f"(acc[l][mi][ni][1]),
                              "+f"(acc[l][mi][ni][2]), "+f"(acc[l][mi][ni][3])
                            : "r"(a0), "r"(a1), "r"(a2), "r"(a3),
                              "r"(bf[ks][ni][0]), "r"(bf[ks][ni][1]));
                    }
                }
            }
        }

        // done reading stage cs
        mbar_arrive(su + SM_MBAR + cs * 16 + 8);
        cs++; if (cs == STAGES) { cs = 0; cph ^= 1; }

        // producer: fill chunk ch+4 into stage ps
        if (ch + 4 < NCH) {
            if (ch > 0)   // ch==0 targets fresh stage 4: no wait needed
                mbar_wait(su + SM_MBAR + ps * 16 + 8, pph);
            fill(ps, ch + 4);
            cpa_mbar_arrive(su + SM_MBAR + ps * 16);
            ps++; if (ps == STAGES) { ps = 0; pph ^= 1; }
        }
    }

    // Epilogue: fuse t2_h (+bias) and t2_d for both labels.
#pragma unroll
    for (int l = 0; l < L_PER; l++) {
        const int gl = b * NL + L0 + l;
        size_t obase = (((size_t)gl) * NS + i0) * NS + o0;
        const float* th_p = g_t2h + (size_t)gl * NS + i0;
        const float* td_p = g_t2d + (size_t)gl * NS + o0;
#pragma unroll
        for (int mi = 0; mi < 2; mi++) {
            int r = rbase + mi * 16 + (lane >> 2);
            float th0 = th_p[r];
            float th1 = th_p[r + 8];
#pragma unroll
            for (int ni = 0; ni < 4; ni++) {
                int c = cbase + ni * 8 + (lane & 3) * 2;
                float td0 = td_p[c];
                float td1 = td_p[c + 1];
                float2 v0 = make_float2(acc[l][mi][ni][0] + th0 + td0,
                                        acc[l][mi][ni][1] + th0 + td1);
                float2 v1 = make_float2(acc[l][mi][ni][2] + th1 + td0,
                                        acc[l][mi][ni][3] + th1 + td1);
                *(float2*)(out + obase + (size_t)r * NS + c) = v0;
                *(float2*)(out + obase + (size_t)(r + 8) * NS + c) = v1;
            }
        }
    }
}

extern "C" void kernel_launch(void* const* d_in, const int* in_sizes, int n_in,
                              void* d_out, int out_size) {
    const float* head = (const float*)d_in[0];
    const float* dep  = (const float*)d_in[1];
    const float* U    = (const float*)d_in[2];
    const float* W    = (const float*)d_in[3];
    const float* bias = (const float*)d_in[4];
    float* out = (float*)d_out;

    cudaFuncSetAttribute(biaffine_main,
                         cudaFuncAttributeMaxDynamicSharedMemorySize, SMEM_TOTAL);

    prep_kernel<<<640, 256>>>(head, dep, U, W, bias);
    biaffine_main<<<dim3(32, NL / L_PER, NB), THREADS, SMEM_TOTAL>>>(out);
}

// round 16
// speedup vs baseline: 1.0699x; 1.0699x over previous
#include <cuda_runtime.h>
#include <cuda_fp16.h>
#include <cstdint>

#define NB 4
#define NS 512
#define ND 768
#define NL 64
#define KC 32
#define NCH 24           // 768 / 32
#define STAGES 5
#define THREADS 256
#define L_PER 2

// fp16 copies of inputs + rank-1 terms (bias folded into g_t2h)
__device__ float  g_t2h[NB * NL * NS];
__device__ float  g_t2d[NB * NL * NS];
__device__ __half g_head_h[(size_t)NB * NS * ND];
__device__ __half g_dep_h[(size_t)NB * NS * ND];
__device__ __half g_U_h[NL * ND];

// smem: U rows (2*768*2=3072B) | mbar pairs (5*16=80, pad to 128) | 5 stages of
// [A 128x32 pitch40 (10240B) | B 64x32 pitch40 (5120B)]
#define SM_U     0
#define SM_MBAR  3072
#define SM_TILES 3200
#define A_BYTES  10240
#define STAGE_BYTES 15360
#define SMEM_TOTAL (SM_TILES + STAGES * STAGE_BYTES)   // 80000 -> 2 CTAs/SM

static __device__ __forceinline__ uint32_t s2u(const void* p) {
    uint32_t a;
    asm("{ .reg .u64 t; cvta.to.shared.u64 t, %1; cvt.u32.u64 %0, t; }"
        : "=r"(a) : "l"(p));
    return a;
}
static __device__ __forceinline__ void cpa16(uint32_t s, const void* g) {
    asm volatile("cp.async.cg.shared.global [%0], [%1], 16;" :: "r"(s), "l"(g));
}
static __device__ __forceinline__ void mbar_init(uint32_t a, uint32_t cnt) {
    asm volatile("mbarrier.init.shared.b64 [%0], %1;" :: "r"(a), "r"(cnt) : "memory");
}
static __device__ __forceinline__ void mbar_arrive(uint32_t a) {
    asm volatile("mbarrier.arrive.shared.b64 _, [%0];" :: "r"(a) : "memory");
}
static __device__ __forceinline__ void cpa_mbar_arrive(uint32_t a) {
    asm volatile("cp.async.mbarrier.arrive.noinc.shared.b64 [%0];"
                 :: "r"(a) : "memory");
}
static __device__ __forceinline__ void mbar_wait(uint32_t a, uint32_t parity) {
    asm volatile(
        "{\n\t.reg .pred P;\n\t"
        "WL_%=:\n\t"
        "mbarrier.try_wait.parity.acquire.cta.shared::cta.b64 P, [%0], %1, 0x989680;\n\t"
        "@P bra.uni WD_%=;\n\t"
        "bra.uni WL_%=;\n\t"
        "WD_%=:\n\t}"
        :: "r"(a), "r"(parity) : "memory");
}
static __device__ __forceinline__ void ldsm4(uint32_t& r0, uint32_t& r1,
                                             uint32_t& r2, uint32_t& r3,
                                             uint32_t a) {
    asm volatile("ldmatrix.sync.aligned.m8n8.x4.shared.b16 {%0,%1,%2,%3}, [%4];"
                 : "=r"(r0), "=r"(r1), "=r"(r2), "=r"(r3) : "r"(a));
}
static __device__ __forceinline__ unsigned hm2(unsigned a, unsigned b) {
    __half2 x = *reinterpret_cast<__half2*>(&a);
    __half2 y = *reinterpret_cast<__half2*>(&b);
    __half2 r = __hmul2(x, y);
    return *reinterpret_cast<unsigned*>(&r);
}

// ---------------------------------------------------------------------------
// prep_kernel: blocks [0,128) compute rank-1 terms t2_h (+bias) / t2_d
// (scheduled FIRST so they start in wave 1); blocks [128,640) convert the
// inputs to fp16 (scalar stores — measured faster than the strided-vector
// variant). No ordering dependency between the two halves.
// ---------------------------------------------------------------------------
__global__ void prep_kernel(const float* __restrict__ head,
                            const float* __restrict__ dep,
                            const float* __restrict__ U,
                            const float* __restrict__ W,
                            const float* __restrict__ bias) {
    __shared__ float sX[32][36];
    __shared__ float sW[64][36];

    if (blockIdx.x >= 128) {
        const int cb = blockIdx.x - 128;            // 0..511
        size_t n = (size_t)NB * NS * ND;
        size_t stride = (size_t)512 * blockDim.x;
        for (size_t i = cb * (size_t)blockDim.x + threadIdx.x; i < n;
             i += stride) {
            g_head_h[i] = __float2half_rn(head[i]);
            g_dep_h[i]  = __float2half_rn(dep[i]);
        }
        for (size_t i = cb * (size_t)blockDim.x + threadIdx.x;
             i < (size_t)NL * ND; i += stride)
            g_U_h[i] = __float2half_rn(U[i]);
        return;
    }

    int idx = blockIdx.x;                // 0..127
    int type = idx >> 6;                 // 0 = head/Wh, 1 = dep/Wd
    int b = (idx >> 4) & 3;
    int s0 = (idx & 15) * 32;
    const float* X = type ? dep : head;
    float* out = type ? g_t2d : g_t2h;
    int woff = type ? ND : 0;

    int t = threadIdx.x;
    int row = t >> 3, c4 = (t & 7) * 4;
    int ty = t >> 4, tx = t & 15;
    float acc[2][4] = {};

    for (int k0 = 0; k0 < ND; k0 += 32) {
        *(float4*)&sX[row][c4] =
            *(const float4*)&X[(size_t)(b * NS + s0 + row) * ND + k0 + c4];
        *(float4*)&sW[row][c4] =
            *(const float4*)&W[(size_t)row * (2 * ND) + woff + k0 + c4];
        *(float4*)&sW[row + 32][c4] =
            *(const float4*)&W[(size_t)(row + 32) * (2 * ND) + woff + k0 + c4];
        __syncthreads();
#pragma unroll
        for (int kk = 0; kk < 32; kk++) {
            float x0 = sX[ty * 2 + 0][kk];
            float x1 = sX[ty * 2 + 1][kk];
#pragma unroll
            for (int j = 0; j < 4; j++) {
                float w = sW[tx + 16 * j][kk];
                acc[0][j] += x0 * w;
                acc[1][j] += x1 * w;
            }
        }
        __syncthreads();
    }
#pragma unroll
    for (int rr = 0; rr < 2; rr++) {
        int s = s0 + ty * 2 + rr;
#pragma unroll
        for (int j = 0; j < 4; j++) {
            int ll = tx + 16 * j;
            float v = acc[rr][j];
            if (type == 0) v += bias[ll];
            out[(size_t)(b * NL + ll) * NS + s] = v;
        }
    }
}

// ---------------------------------------------------------------------------
// Main: per CTA: (b, 2 labels, 128 i x 64 o).
//   out[l] = (head*U[L0+l]) @ dep^T + t2 terms, l = 0,1.
// A (head) and B (dep) fragments are label-independent -> LDSM once, MMA
// twice (per-label U scaling via 4 reused HMUL2 temps). Acc stays 64 floats.
// 256 threads, 8 warps 4m x 2n, per-label warp tile 32x32, f32 acc.
// KC=32, 5 stages, 4 fills ahead, per-stage full/empty mbarriers. 2 CTAs/SM.
// ---------------------------------------------------------------------------
__global__ void __launch_bounds__(THREADS, 2) biaffine_main(float* __restrict__ out) {
    extern __shared__ char smem[];
    const uint32_t su = s2u(smem);
    __half* sU = (__half*)(smem + SM_U);

    const int tid = threadIdx.x;
    const int lane = tid & 31;
    const int wid = tid >> 5;
    const int rbase = (wid & 3) * 32;       // 4 warps in m (128 rows)
    const int cbase = (wid >> 2) * 32;      // 2 warps in n (64 cols)

    const int L0 = blockIdx.y * L_PER;
    const int b  = blockIdx.z;
    const int i0 = (blockIdx.x >> 3) * 128;
    const int o0 = (blockIdx.x & 7) * 64;

    // mbar layout: full[s] @ SM_MBAR+16s, empty[s] @ SM_MBAR+16s+8
    if (tid == 0) {
#pragma unroll
        for (int s = 0; s < STAGES; s++) {
            mbar_init(su + SM_MBAR + s * 16,     THREADS);  // full
            mbar_init(su + SM_MBAR + s * 16 + 8, THREADS);  // empty
        }
    }

    // Fill mapping.
    // A (128 rows x 32 halves): 2 threads/row, 16 halves each (2 cp16).
    const int frow = tid >> 1;
    const int fh = (tid & 1) * 16;
    const __half* gA = g_head_h + ((size_t)(b * NS + i0 + frow)) * ND + fh;
    const uint32_t sfA = su + SM_TILES + (frow * 40 + fh) * 2;
    // B (64 rows x 32 halves): 4 threads/row, 8 halves each (1 cp16).
    const int brow = tid >> 2;
    const int bh = (tid & 3) * 8;
    const __half* gB = g_dep_h + ((size_t)(b * NS + o0 + brow)) * ND + bh;
    const uint32_t sfB = su + SM_TILES + A_BYTES + (brow * 40 + bh) * 2;

    auto fill = [&](int s, int ch) {
        const int k0 = ch * KC;
        const uint32_t so = s * STAGE_BYTES;
        cpa16(sfA + so,      gA + k0);
        cpa16(sfA + so + 16, gA + k0 + 8);
        cpa16(sfB + so,      gB + k0);
    };

    // U rows for both labels (contiguous in g_U_h)
    {
        const uint32_t* gU = (const uint32_t*)(g_U_h + (size_t)L0 * ND);
        for (int j = tid; j < L_PER * ND / 2; j += THREADS)
            ((uint32_t*)sU)[j] = gU[j];
    }
    __syncthreads();   // mbar init + sU visible to all

    // Prologue: fill stages 0..3 (fresh, no empty wait needed).
#pragma unroll
    for (int p = 0; p < 4; p++) {
        fill(p, p);
        cpa_mbar_arrive(su + SM_MBAR + p * 16);
    }

    float acc[L_PER][2][4][4];
#pragma unroll
    for (int l = 0; l < L_PER; l++)
#pragma unroll
        for (int mi = 0; mi < 2; mi++)
#pragma unroll
            for (int ni = 0; ni < 4; ni++)
#pragma unroll
                for (int k = 0; k < 4; k++) acc[l][mi][ni][k] = 0.0f;

    const int lrow = (lane & 7) + ((lane >> 3) & 1) * 8;
    const int lcol = (lane >> 4) * 8;
    const int c0 = (lane & 3) * 2;

    int cs = 0, cph = 0;     // consumer stage/phase
    int ps = 4, pph = 1;     // producer: next fill = chunk 4 -> stage 4
    for (int ch = 0; ch < NCH; ch++) {
        // consumer: wait chunk ch ready
        mbar_wait(su + SM_MBAR + cs * 16, cph);

        const uint32_t aB = su + SM_TILES + cs * STAGE_BYTES;
        const uint32_t bB = aB + A_BYTES;

#pragma unroll
        for (int ks = 0; ks < 2; ks++) {
            const int kb = ks * 16;
            const int kg = ch * KC + kb;

            // Raw (unscaled) A fragments: 2 m16 tiles.
            unsigned af[2][4];
#pragma unroll
            for (int mi = 0; mi < 2; mi++) {
                uint32_t a = aB + ((rbase + mi * 16 + lrow) * 40 + kb + lcol) * 2;
                ldsm4(af[mi][0], af[mi][1], af[mi][2], af[mi][3], a);
            }
            // B fragments: 4 n8 tiles (2 ldsm4 over 32 cols).
            unsigned bf[4][2];
#pragma unroll
            for (int g = 0; g < 2; g++) {
                uint32_t a = bB + ((cbase + g * 16 + lrow) * 40 + kb + lcol) * 2;
                ldsm4(bf[2 * g][0], bf[2 * g + 1][0], bf[2 * g][1], bf[2 * g + 1][1], a);
            }

            // Per label: scale A fragments with U[L0+l], run 8 MMAs.
#pragma unroll
            for (int l = 0; l < L_PER; l++) {
                unsigned ulo = *(const unsigned*)&sU[l * ND + kg + c0];
                unsigned uhi = *(const unsigned*)&sU[l * ND + kg + c0 + 8];
#pragma unroll
                for (int mi = 0; mi < 2; mi++) {
                    unsigned a0 = hm2(af[mi][0], ulo);
                    unsigned a1 = hm2(af[mi][1], ulo);
                    unsigned a2 = hm2(af[mi][2], uhi);
                    unsigned a3 = hm2(af[mi][3], uhi);
#pragma unroll
                    for (int ni = 0; ni < 4; ni++) {
                        asm volatile(
                            "mma.sync.aligned.m16n8k16.row.col.f32.f16.f16.f32 "
                            "{%0,%1,%2,%3}, {%4,%5,%6,%7}, {%8,%9}, {%0,%1,%2,%3};"
                            : "+f"(acc[l][mi][ni][0]), "+f"(acc[l][mi][ni][1]),
                              "+f"(acc[l][mi][ni][2]), "+f"(acc[l][mi][ni][3])
                            : "r"(a0), "r"(a1), "r"(a2), "r"(a3),
                              "r"(bf[ni][0]), "r"(bf[ni][1]));
                    }
                }
            }
        }

        // done reading stage cs (in-order issue: MMAs consumed all LDSM results)
        mbar_arrive(su + SM_MBAR + cs * 16 + 8);
        cs++; if (cs == STAGES) { cs = 0; cph ^= 1; }

        // producer: fill chunk ch+4 into stage ps
        if (ch + 4 < NCH) {
            if (ch > 0)   // ch==0 targets fresh stage 4: no wait needed
                mbar_wait(su + SM_MBAR + ps * 16 + 8, pph);
            fill(ps, ch + 4);
            cpa_mbar_arrive(su + SM_MBAR + ps * 16);
            ps++; if (ps == STAGES) { ps = 0; pph ^= 1; }
        }
    }

    // Epilogue: fuse t2_h (+bias) and t2_d for both labels.
#pragma unroll
    for (int l = 0; l < L_PER; l++) {
        const int gl = b * NL + L0 + l;
        size_t obase = (((size_t)gl) * NS + i0) * NS + o0;
        const float* th_p = g_t2h + (size_t)gl * NS + i0;
        const float* td_p = g_t2d + (size_t)gl * NS + o0;
#pragma unroll
        for (int mi = 0; mi < 2; mi++) {
            int r = rbase + mi * 16 + (lane >> 2);
            float th0 = th_p[r];
            float th1 = th_p[r + 8];
#pragma unroll
            for (int ni = 0; ni < 4; ni++) {
                int c = cbase + ni * 8 + (lane & 3) * 2;
                float td0 = td_p[c];
                float td1 = td_p[c + 1];
                float2 v0 = make_float2(acc[l][mi][ni][0] + th0 + td0,
                                        acc[l][mi][ni][1] + th0 + td1);
                float2 v1 = make_float2(acc[l][mi][ni][2] + th1 + td0,
                                        acc[l][mi][ni][3] + th1 + td1);
                *(float2*)(out + obase + (size_t)r * NS + c) = v0;
                *(float2*)(out + obase + (size_t)(r + 8) * NS + c) = v1;
            }
        }
    }
}

extern "C" void kernel_launch(void* const* d_in, const int* in_sizes, int n_in,
                              void* d_out, int out_size) {
    const float* head = (const float*)d_in[0];
    const float* dep  = (const float*)d_in[1];
    const float* U    = (const float*)d_in[2];
    const float* W    = (const float*)d_in[3];
    const float* bias = (const float*)d_in[4];
    float* out = (float*)d_out;

    cudaFuncSetAttribute(biaffine_main,
                         cudaFuncAttributeMaxDynamicSharedMemorySize, SMEM_TOTAL);

    prep_kernel<<<640, 256>>>(head, dep, U, W, bias);
    biaffine_main<<<dim3(32, NL / L_PER, NB), THREADS, SMEM_TOTAL>>>(out);
}